// round 17
// baseline (speedup 1.0000x reference)
#include <cuda_runtime.h>
#include <cstdint>

#define BATCH 4
#define NPTS  8192
#define NQ    (2 * BATCH * NPTS)  // 65536 points total (both sets)
#define GDIM  64
#define NCELL (GDIM * GDIM)       // 4096
#define CAP   20                  // lambda=2; P(overflow)~1e-12
#define HCELL (1.0f / GDIM)
#define NTAB  (2 * BATCH)         // 8 tables: tab = s*BATCH+b; opposite = tab^4
#define TASKS (NTAB * NCELL)      // 32768 (both directions covered)
#define NTHR  256
#define TPW   4                   // tasks per warp
#define NSB   (TASKS / (8 * TPW)) // 1024 search blocks
#define FINF  3.4e38f
#define FULL  0xFFFFFFFFu

// Persistent scratch (zero at load; search's last block re-zeros counts).
// Slots beyond a cell's count are stale-but-finite; all reads predicated.
__device__ int      g_ccnt[NTAB * NCELL];
__device__ float2   g_cell[NTAB * NCELL * CAP];    // 5.2 MB (L2-resident)
__device__ float    g_part[NSB];
__device__ unsigned g_done;

__device__ __forceinline__ int clampi(int v) { return min(GDIM - 1, max(0, v)); }

// ============================================================================
// K1: bin all points (atomicAdd slot; drop on overflow - P~0)
// ============================================================================
__global__ __launch_bounds__(NTHR) void k_fill(const float2* __restrict__ pred,
                                               const float2* __restrict__ gt) {
    int gid = blockIdx.x * NTHR + threadIdx.x;
    int s = gid >> 15, b = (gid >> 13) & 3, i = gid & (NPTS - 1);
    const float2* src = s ? gt : pred;
    float2 p = src[b * NPTS + i];
    int cx = clampi((int)(p.x * (float)GDIM));
    int cy = clampi((int)(p.y * (float)GDIM));
    int cell = (s * BATCH + b) * NCELL + cy * GDIM + cx;
    int pos = atomicAdd(&g_ccnt[cell], 1);
    if (pos < CAP) g_cell[cell * CAP + pos] = p;
}

__device__ __forceinline__ void scan_cell(int base, int c, float qx, float qy,
                                          float& best) {
    int n = min(g_ccnt[base + c], CAP);
    const float2* p = &g_cell[(base + c) * CAP];
    for (int j = 0; j < n; j++) {
        float dx = qx - p[j].x, dy = qy - p[j].y;
        best = fminf(best, fmaf(dx, dx, dy * dy));
    }
}

// Expanding Chebyshev rings, k>=2 (ring-k cells are >= (k-1)*H away -> exact).
__device__ float ring_search(int base, int cx, int cy, float qx, float qy,
                             float best) {
    #pragma unroll 1
    for (int k = 2; k < GDIM; k++) {
        float rd = (float)(k - 1) * HCELL;
        if (best <= rd * rd) break;
        int y0 = max(cy - k, 0), y1 = min(cy + k, GDIM - 1);
        int x0 = max(cx - k, 0), x1 = min(cx + k, GDIM - 1);
        for (int yy = y0; yy <= y1; yy++) {
            if (yy == cy - k || yy == cy + k) {
                for (int xx = x0; xx <= x1; xx++)
                    scan_cell(base, yy * GDIM + xx, qx, qy, best);
            } else {
                if (cx - k >= 0)   scan_cell(base, yy * GDIM + cx - k, qx, qy, best);
                if (cx + k < GDIM) scan_cell(base, yy * GDIM + cx + k, qx, qy, best);
            }
        }
    }
    return best;
}

// ============================================================================
// K2: cell-centric exact NN. One WARP per (tab, cell) task; TPW tasks/warp.
// The queries of a cell are its own binned contents; candidates are the 3x3
// neighborhood of the OPPOSITE table (tab^4). Speculative per-lane coverage
// (3 candidates/lane) spans slots 0..10 (cells 0-4) / 0..9 (cells 5-8) of the
// 9 neighbor cells; all loads at count-independent addresses (front-batched).
// Per query: broadcast + predicated distances + 5-shfl warp min. Straggler
// (best > H^2; P~0.2%): warp-uniform branch, lane 0 rings. Per-cell sum
// extracted in ASCENDING VALUE order -> independent of atomic fill order.
// Coverage overflow (P~4e-5/task): lane 0 serial recompute.
// ============================================================================
__global__ __launch_bounds__(NTHR) void k_search(float* __restrict__ out) {
    const int t = threadIdx.x, bid = blockIdx.x;
    const int w = t >> 5, lane = t & 31;

    // Lane-constant candidate assignments: (cell-index 0..8 in 3x3, slot)
    // A: cells 0..7 slots 0..3 | B: cell8 slots0-3 / cells0-8 slots4-6 (+0,7)
    // C: cells 0..8 slots 7..9 / cells 0..4 slot 10
    const int cAi = lane >> 2,            sA = lane & 3;
    const int cBi = (lane < 4) ? 8 : ((lane - 4) % 9);
    const int sB  = (lane < 4) ? lane : (4 + (lane - 4) / 9);
    const int cCi = (lane < 27) ? (lane % 9) : (lane - 27);
    const int sC  = (lane < 27) ? (7 + lane / 9) : 10;
    const int oxA = cAi % 3 - 1, oyA = cAi / 3 - 1;
    const int oxB = cBi % 3 - 1, oyB = cBi / 3 - 1;
    const int oxC = cCi % 3 - 1, oyC = cCi / 3 - 1;
    const int cNi = min(lane, 8);                      // for coverage check
    const int oxN = cNi % 3 - 1, oyN = cNi / 3 - 1;
    const int covered = (lane < 5) ? 11 : 10;          // cells 0-4: slots 0..10

    float wsum = 0.0f;

    #pragma unroll 1
    for (int j = 0; j < TPW; j++) {
        const int task = (bid * 8 + w) * TPW + j;      // 0..32767
        const int tab = task >> 12, cell = task & (NCELL - 1);
        const int cx = cell & (GDIM - 1), cy = cell >> 6;
        const int own = tab * NCELL;
        const int opp = (tab ^ 4) * NCELL;

        const int cA = clampi(cy + oyA) * GDIM + clampi(cx + oxA);
        const int cB = clampi(cy + oyB) * GDIM + clampi(cx + oxB);
        const int cC = clampi(cy + oyC) * GDIM + clampi(cx + oxC);
        const int cN = clampi(cy + oyN) * GDIM + clampi(cx + oxN);

        // Front-batched independent loads (addresses count-independent)
        int nq = g_ccnt[own + cell];
        const int nA = g_ccnt[opp + cA];
        const int nB = g_ccnt[opp + cB];
        const int nC = g_ccnt[opp + cC];
        const int nN = g_ccnt[opp + cN];
        const float2 qown = g_cell[(own + cell) * CAP + min(lane, CAP - 1)];
        const float2 pA = g_cell[(opp + cA) * CAP + sA];
        const float2 pB = g_cell[(opp + cB) * CAP + sB];
        const float2 pC = g_cell[(opp + cC) * CAP + sC];

        const bool fb = __ballot_sync(FULL, lane < 9 && nN > covered) != 0;
        if (nq == 0) continue;                          // warp-uniform
        nq = min(nq, CAP);

        if (fb) {                                       // ultra-rare serial
            if (lane == 0) {
                float bests[CAP];
                for (int qi = 0; qi < nq; qi++) {
                    float2 q = g_cell[(own + cell) * CAP + qi];
                    float best = FINF;
                    for (int e = 0; e < 9; e++) {
                        int c = clampi(cy + e / 3 - 1) * GDIM + clampi(cx + e % 3 - 1);
                        scan_cell(opp, c, q.x, q.y, best);
                    }
                    if (best > HCELL * HCELL)
                        best = ring_search(opp, cx, cy, q.x, q.y, best);
                    bests[qi] = best;
                }
                // ascending-order sum (multiset-deterministic)
                for (int a = 1; a < nq; a++) {          // insertion sort
                    float v = bests[a]; int k2 = a - 1;
                    while (k2 >= 0 && bests[k2] > v) { bests[k2 + 1] = bests[k2]; k2--; }
                    bests[k2 + 1] = v;
                }
                float acc = 0.0f;
                for (int a = 0; a < nq; a++) acc += bests[a];
                wsum += acc;                            // only lane 0's wsum is read
            }
            continue;
        }

        float mybest = FINF;
        for (int qi = 0; qi < nq; qi++) {
            const float qx = __shfl_sync(FULL, qown.x, qi);
            const float qy = __shfl_sync(FULL, qown.y, qi);
            float d = FINF, dx, dy, dd;
            dx = qx - pA.x; dy = qy - pA.y; dd = fmaf(dx, dx, dy * dy);
            d = fminf(d, (sA < nA) ? dd : FINF);
            dx = qx - pB.x; dy = qy - pB.y; dd = fmaf(dx, dx, dy * dy);
            d = fminf(d, (sB < nB) ? dd : FINF);
            dx = qx - pC.x; dy = qy - pC.y; dd = fmaf(dx, dx, dy * dy);
            d = fminf(d, (sC < nC) ? dd : FINF);
            #pragma unroll
            for (int off = 16; off > 0; off >>= 1)
                d = fminf(d, __shfl_xor_sync(FULL, d, off));
            if (d > HCELL * HCELL) {                    // uniform (d same all lanes)
                if (lane == 0) d = ring_search(opp, cx, cy, qx, qy, d);
                d = __shfl_sync(FULL, d, 0);
            }
            if (lane == qi) mybest = d;
        }

        // Deterministic per-cell sum: extract bests in ascending value order
        float v = (lane < nq) ? mybest : FINF;
        float acc = 0.0f;
        for (int it = 0; it < nq; it++) {
            float m = v;
            #pragma unroll
            for (int off = 16; off > 0; off >>= 1)
                m = fminf(m, __shfl_xor_sync(FULL, m, off));
            acc += m;
            unsigned eq = __ballot_sync(FULL, v == m);
            if (lane == __ffs(eq) - 1) v = FINF;
        }
        wsum += acc;
    }

    // ---- Block partial (8 warps, fixed order) + last-block finalization ----
    __shared__ float sw[8];
    __shared__ unsigned lastf;
    if (lane == 0) sw[w] = wsum;
    __syncthreads();
    if (t == 0) {
        float a = 0.0f;
        #pragma unroll
        for (int k = 0; k < 8; k++) a += sw[k];
        g_part[bid] = a;
        __threadfence();
        lastf = (atomicAdd(&g_done, 1u) == NSB - 1) ? 1u : 0u;
    }
    __syncthreads();

    if (lastf) {
        __threadfence();
        __shared__ float sm[NTHR];
        float a = 0.0f;
        #pragma unroll
        for (int k = 0; k < NSB / NTHR; k++)
            a += ((volatile float*)g_part)[t + k * NTHR];
        sm[t] = a;
        __syncthreads();
        for (int off = NTHR / 2; off > 0; off >>= 1) {
            if (t < off) sm[t] += sm[t + off];
            __syncthreads();
        }
        if (t == 0) {
            out[0] = sm[0] * (1.0f / (float)(BATCH * NPTS));
            g_done = 0;
        }
        int4* cc = (int4*)g_ccnt;
        #pragma unroll 4
        for (int k = t; k < NTAB * NCELL / 4; k += NTHR)
            cc[k] = make_int4(0, 0, 0, 0);
    }
}

extern "C" void kernel_launch(void* const* d_in, const int* in_sizes, int n_in,
                              void* d_out, int out_size) {
    const float2* pred = (const float2*)d_in[0];
    const float2* gt   = (const float2*)d_in[1];

    k_fill<<<NQ / NTHR, NTHR>>>(pred, gt);
    k_search<<<NSB, NTHR>>>((float*)d_out);
}